// round 12
// baseline (speedup 1.0000x reference)
#include <cuda_runtime.h>
#include <cuda_fp16.h>

// B=256, T_MAX=D_MAX=256, TP=DP=257
#define NTHREADS 512
#define L_PAD    66049          // 257*257
#define EPS_C    1e-12f

// Shared layout (floats)
#define U_OFF    0              // u[260]
#define V_OFF    260            // v[260]
#define RMAX_OFF 520            // row max [260]     (reused as cost[] during remap)
#define RHAS_OFF 780            // row-has-assignment flags [260]
#define CMAX_OFF 1040           // col max [260]
#define SUP_OFF  1300           // per-warp sum(u) partials [16]
#define SVP_OFF  1316           // per-warp sum(v) partials [16]
#define SCR_OFF  1332           // fp32 half-split combine scratch [256]
#define SCR2_OFF 1588           // fp16 quarter-combine scratch [768] (3 x 256)
#define PICK_OFF 2356           // chosen example index [1]
#define K_OFF    2360
#define SMEM_FLOATS 58112       // 232448 B / 4
#define KCAP     (SMEM_FLOATS - K_OFF)   // 55752 fp32 slots
#define SMEM_BYTES (SMEM_FLOATS * 4)

// Deterministic 3-way product: bit-identical across all transport recomputes.
__device__ __forceinline__ float tmul3(float u, float k, float v) {
    return __fmul_rn(__fmul_rn(u, k), v);
}

template<bool F32>
__device__ void run_ex(const float* __restrict__ aff, int nt, int nd,
                       float* __restrict__ oT, float* __restrict__ oA,
                       float* sm)
{
    const int tid  = threadIdx.x;
    const int lane = tid & 31;
    const int w    = tid >> 5;

    // Row pitch: odd multiple of 4 (fp32) / 8 (fp16). (Pass 1 is now
    // warp-per-row contiguous, so the pitch no longer causes conflicts.)
    int ndp;
    if (F32) { ndp = (nd + 3) & ~3; if (((ndp >> 2) & 1) == 0) ndp += 4; }
    else     { ndp = (nd + 7) & ~7; if (((ndp >> 3) & 1) == 0) ndp += 8; }

    float*  u_s    = sm + U_OFF;
    float*  v_s    = sm + V_OFF;
    float*  rmax_s = sm + RMAX_OFF;
    float*  rhas   = sm + RHAS_OFF;
    float*  cmax_s = sm + CMAX_OFF;
    float*  sup    = sm + SUP_OFF;
    float*  svp    = sm + SVP_OFF;
    float*  scr    = sm + SCR_OFF;
    float*  scr2   = sm + SCR2_OFF;
    float*  Kf     = sm + K_OFF;
    __half* Kh     = (__half*)(sm + K_OFF);

    // ---- Pass-1 lane chunks (warp-per-row, contiguous lanes) ----
    // fp32: lane covers floats [4l,4l+3] and [128+4l,128+4l+3] (+[256..259] lane0)
    // fp16: lane covers halves [8l..8l+7] (+[256..263] lane0)
    const int  c0w = F32 ? 4 * lane : 8 * lane;
    const int  c1w = 4 * lane + 128;                    // fp32 only
    const bool k0  = c0w < ndp;
    const bool k1  = F32 && (c1w < ndp);
    const bool k2  = (lane == 0) && (ndp > 256);        // tail chunk

    // fp32 pass-2 / epilogue identities (half rows per column) — proven R8.
    const int  nth   = (nt >> 1) & ~3;
    const int  col   = tid & 255;
    const bool up    = tid >= 256;
    const bool colok = col < nd;
    const int  p2beg = up ? nth : 0;
    const int  p2end = up ? nt  : nth;

    // fp16 pass-2 / epilogue identities: column pair x row quarter — proven R9.
    const int cp   = tid & 127;
    const int qq   = tid >> 7;
    const int c0   = 2 * cp, c1 = 2 * cp + 1;
    const int qb1  = (nt >> 2) & ~3;
    const int qb2  = (nt >> 1) & ~3;
    const int qb3  = ((3 * nt) >> 2) & ~3;
    const int rqb  = (qq == 0) ? 0   : (qq == 1) ? qb1 : (qq == 2) ? qb2 : qb3;
    const int rqe  = (qq == 0) ? qb1 : (qq == 1) ? qb2 : (qq == 2) ? qb3 : nt;
    const int ndp_2 = ndp >> 1;

    // ---- Pre-zero K region (padding must be exactly 0) ----
    const int kwords = F32 ? nt * ndp : (nt * ndp) >> 1;
    for (int i = tid * 4; i < kwords; i += NTHREADS * 4)
        *(float4*)(Kf + i) = make_float4(0.f, 0.f, 0.f, 0.f);

    // init v0 = 1 on c<=nd; svp holds interior sum only (= nd).
    for (int c = tid; c < 260; c += NTHREADS) v_s[c] = (c <= nd) ? 1.f : 0.f;
    if (tid < 16) svp[tid] = (tid == 0) ? (float)nd : 0.f;
    __syncthreads();

    // ---- Build K = exp(10*aff) on interior (contiguous lanes) ----
    {
        const int cq0 = F32 ? 4 * lane : 8 * lane;
        const int cq1 = 4 * lane + 128;
        for (int r = w; r < nt; r += 16) {
            const float* arow = aff + (size_t)r * 256;
            if (F32) {
                float* krow = Kf + (size_t)r * ndp;
                if (cq0 < nd) {
                    float x[4];
                    #pragma unroll
                    for (int i = 0; i < 4; i++) { int c = cq0 + i; x[i] = (c < nd) ? __expf(10.0f * arow[c]) : 0.f; }
                    *(float4*)(krow + cq0) = make_float4(x[0], x[1], x[2], x[3]);
                }
                if (cq1 < nd) {
                    float x[4];
                    #pragma unroll
                    for (int i = 0; i < 4; i++) { int c = cq1 + i; x[i] = (c < nd) ? __expf(10.0f * arow[c]) : 0.f; }
                    *(float4*)(krow + cq1) = make_float4(x[0], x[1], x[2], x[3]);
                }
            } else {
                __half* krow = Kh + (size_t)r * ndp;
                if (cq0 < nd) {
                    __half h[8];
                    #pragma unroll
                    for (int i = 0; i < 8; i++) { int c = cq0 + i; h[i] = __float2half_rn((c < nd) ? __expf(10.0f * arow[c]) : 0.f); }
                    *(uint4*)(krow + cq0) = *(uint4*)h;
                }
            }
        }
    }
    __syncthreads();

    const float ndf = (float)nd, ntf = (float)nt;
    const int   ndpS = ndp, ndp2b = 2 * ndp, ndp3b = 3 * ndp, ndp4s = 4 * ndp;
    const float4 f4z = make_float4(0.f, 0.f, 0.f, 0.f);

    // ================= 100 Sinkhorn iterations =================
    for (int it = 0; it < 100; ++it) {
        // ---- Pass 1 (warp-per-row): u_r = 1/((Kv)_r + v[nd] + eps) ----
        float sumv = v_s[nd];
        #pragma unroll
        for (int k = 0; k < 16; k++) sumv += svp[k];
        const float u_top = ndf / (sumv + EPS_C);
        const float v_dum = v_s[nd];

        float usum = 0.f;
        if (F32) {
            const float4 vv0 = k0 ? *(const float4*)(v_s + c0w) : f4z;
            const float4 vv1 = k1 ? *(const float4*)(v_s + c1w) : f4z;
            const float4 vv2 = k2 ? *(const float4*)(v_s + 256) : f4z;
            for (int r = w; r < nt; r += 16) {
                const float* krow = Kf + (size_t)r * ndp;
                float4 kk0 = k0 ? *(const float4*)(krow + c0w) : f4z;
                float4 kk1 = k1 ? *(const float4*)(krow + c1w) : f4z;
                float4 kk2 = k2 ? *(const float4*)(krow + 256) : f4z;
                float a0 = fmaf(kk0.x, vv0.x, fmaf(kk1.x, vv1.x, kk2.x * vv2.x));
                float a1 = fmaf(kk0.y, vv0.y, fmaf(kk1.y, vv1.y, kk2.y * vv2.y));
                float a2 = fmaf(kk0.z, vv0.z, fmaf(kk1.z, vv1.z, kk2.z * vv2.z));
                float a3 = fmaf(kk0.w, vv0.w, fmaf(kk1.w, vv1.w, kk2.w * vv2.w));
                float dot = (a0 + a1) + (a2 + a3);
                #pragma unroll
                for (int o = 16; o > 0; o >>= 1) dot += __shfl_xor_sync(0xffffffffu, dot, o);
                if (lane == 0) {
                    float u = 1.0f / (dot + v_dum + EPS_C);
                    u_s[r] = u; usum += u;
                }
            }
        } else {
            const float4 va0 = k0 ? *(const float4*)(v_s + c0w)     : f4z;
            const float4 va1 = k0 ? *(const float4*)(v_s + c0w + 4) : f4z;
            const float4 vb0 = k2 ? *(const float4*)(v_s + 256)     : f4z;  // halves 256-259
            const float4 vb1 = k2 ? *(const float4*)(sm + V_OFF + 260 - 260 + 260) : f4z; // unused safe slot
            for (int r = w; r < nt; r += 16) {
                const __half* krow = Kh + (size_t)r * ndp;
                float a0 = 0.f, a1 = 0.f, a2 = 0.f, a3 = 0.f;
                if (k0) {
                    uint4 raw = *(const uint4*)(krow + c0w);
                    float2 f;
                    f = __half22float2(*(__half2*)&raw.x); a0 = fmaf(f.x, va0.x, a0); a1 = fmaf(f.y, va0.y, a1);
                    f = __half22float2(*(__half2*)&raw.y); a2 = fmaf(f.x, va0.z, a2); a3 = fmaf(f.y, va0.w, a3);
                    f = __half22float2(*(__half2*)&raw.z); a0 = fmaf(f.x, va1.x, a0); a1 = fmaf(f.y, va1.y, a1);
                    f = __half22float2(*(__half2*)&raw.w); a2 = fmaf(f.x, va1.z, a2); a3 = fmaf(f.y, va1.w, a3);
                }
                if (k2) {
                    // halves 256..263; columns >= 256 are pad (K=0) except none
                    // (nd<=256), so only 256..259 can matter and K pad kills rest.
                    uint4 raw = *(const uint4*)(krow + 256);
                    float2 f;
                    f = __half22float2(*(__half2*)&raw.x); a0 = fmaf(f.x, vb0.x, a0); a1 = fmaf(f.y, vb0.y, a1);
                    f = __half22float2(*(__half2*)&raw.y); a2 = fmaf(f.x, vb0.z, a2); a3 = fmaf(f.y, vb0.w, a3);
                    // halves 260..263 are always pad (K=0): skip.
                }
                float dot = (a0 + a1) + (a2 + a3);
                #pragma unroll
                for (int o = 16; o > 0; o >>= 1) dot += __shfl_xor_sync(0xffffffffu, dot, o);
                if (lane == 0) {
                    float u = 1.0f / (dot + v_dum + EPS_C);
                    u_s[r] = u; usum += u;
                }
            }
        }
        if (lane == 0) sup[w] = usum;
        if (tid == 0) u_s[nt] = u_top;
        __syncthreads();                                   // B2

        // ---- Pass 2: v_c = 1/((K^T u)_c + u_top + eps) ----
        float sumu = u_top;
        #pragma unroll
        for (int k = 0; k < 16; k++) sumu += sup[k];
        const float v_dnew = ntf / (sumu + EPS_C);

        if (F32) {
            float z = 0.f;
            if (colok) {
                float z0 = 0.f, z1 = 0.f, z2 = 0.f, z3 = 0.f;
                const float* p = Kf + col + (size_t)p2beg * ndp;
                int r = p2beg;
                for (; r + 3 < p2end; r += 4) {
                    float4 uu = *(const float4*)(u_s + r);     // broadcast
                    z0 = fmaf(p[0],     uu.x, z0);
                    z1 = fmaf(p[ndpS],  uu.y, z1);
                    z2 = fmaf(p[ndp2b], uu.z, z2);
                    z3 = fmaf(p[ndp3b], uu.w, z3);
                    p += ndp4s;
                }
                for (; r < p2end; r++) { z0 = fmaf(p[0], u_s[r], z0); p += ndpS; }
                z = (z0 + z1) + (z2 + z3);
            }
            if (up && colok) scr[col] = z;
            __syncthreads();                               // B3

            float myv = 0.f;
            if (!up && colok) {
                float zz = (z + scr[col]) + u_top;
                myv = 1.0f / (zz + EPS_C);
                v_s[col] = myv;
            }
            if (tid == 0) v_s[nd] = v_dnew;
            float sv = myv;
            #pragma unroll
            for (int o = 16; o > 0; o >>= 1) sv += __shfl_xor_sync(0xffffffffu, sv, o);
            if (lane == 0) svp[w] = sv;
            __syncthreads();                               // B4
        } else {
            float zxa = 0.f, zya = 0.f, zxb = 0.f, zyb = 0.f;
            {
                const __half2* p = (const __half2*)Kh + (size_t)rqb * ndp_2 + cp;
                int r = rqb;
                for (; r + 3 < rqe; r += 4) {
                    float4 uu = *(const float4*)(u_s + r);
                    float2 kk0 = __half22float2(p[0]);
                    float2 kk1 = __half22float2(p[ndp_2]);
                    float2 kk2 = __half22float2(p[2 * ndp_2]);
                    float2 kk3 = __half22float2(p[3 * ndp_2]);
                    zxa = fmaf(kk0.x, uu.x, zxa); zya = fmaf(kk0.y, uu.x, zya);
                    zxb = fmaf(kk1.x, uu.y, zxb); zyb = fmaf(kk1.y, uu.y, zyb);
                    zxa = fmaf(kk2.x, uu.z, zxa); zya = fmaf(kk2.y, uu.z, zya);
                    zxb = fmaf(kk3.x, uu.w, zxb); zyb = fmaf(kk3.y, uu.w, zyb);
                    p += 4 * ndp_2;
                }
                for (; r < rqe; r++) {
                    float2 kk = __half22float2(p[0]);
                    float  ur = u_s[r];
                    zxa = fmaf(kk.x, ur, zxa); zya = fmaf(kk.y, ur, zya);
                    p += ndp_2;
                }
            }
            float zx = zxa + zxb, zy = zya + zyb;
            if (qq > 0) *(float2*)(scr2 + (size_t)(qq - 1) * 256 + 2 * cp) = make_float2(zx, zy);
            __syncthreads();                               // B3

            float svq = 0.f;
            if (qq == 0) {
                #pragma unroll
                for (int k = 0; k < 3; k++) {
                    float2 o = *(float2*)(scr2 + (size_t)k * 256 + 2 * cp);
                    zx += o.x; zy += o.y;
                }
                if (c0 < nd) { float v0 = 1.0f / ((zx + u_top) + EPS_C); v_s[c0] = v0; svq += v0; }
                if (c1 < nd) { float v1 = 1.0f / ((zy + u_top) + EPS_C); v_s[c1] = v1; svq += v1; }
            }
            if (tid == 0) v_s[nd] = v_dnew;
            #pragma unroll
            for (int o = 16; o > 0; o >>= 1) svq += __shfl_xor_sync(0xffffffffu, svq, o);
            if (lane == 0) svp[w] = svq;
            __syncthreads();                               // B4
        }
    }

    // ================= Epilogue =================
    const float v_dF = v_s[nd];
    const float u_tF = u_s[nt];
    const int   nd1  = nd + 1;

    if (tid < 260) rhas[tid] = 0.f;

    // E1: row max, warp-per-row contiguous + fmaxf butterfly.
    if (F32) {
        const float4 vv0 = k0 ? *(const float4*)(v_s + c0w) : f4z;
        const float4 vv1 = k1 ? *(const float4*)(v_s + c1w) : f4z;
        const float4 vv2 = k2 ? *(const float4*)(v_s + 256) : f4z;
        for (int r = w; r < nt; r += 16) {
            const float* krow = Kf + (size_t)r * ndp;
            const float u = u_s[r];
            float m = 0.f;
            if (k0) {
                float4 kk = *(const float4*)(krow + c0w);
                m = fmaxf(m, tmul3(u, kk.x, vv0.x)); m = fmaxf(m, tmul3(u, kk.y, vv0.y));
                m = fmaxf(m, tmul3(u, kk.z, vv0.z)); m = fmaxf(m, tmul3(u, kk.w, vv0.w));
            }
            if (k1) {
                float4 kk = *(const float4*)(krow + c1w);
                m = fmaxf(m, tmul3(u, kk.x, vv1.x)); m = fmaxf(m, tmul3(u, kk.y, vv1.y));
                m = fmaxf(m, tmul3(u, kk.z, vv1.z)); m = fmaxf(m, tmul3(u, kk.w, vv1.w));
            }
            if (k2) {
                float4 kk = *(const float4*)(krow + 256);
                m = fmaxf(m, tmul3(u, kk.x, vv2.x)); m = fmaxf(m, tmul3(u, kk.y, vv2.y));
                m = fmaxf(m, tmul3(u, kk.z, vv2.z)); m = fmaxf(m, tmul3(u, kk.w, vv2.w));
            }
            #pragma unroll
            for (int o = 16; o > 0; o >>= 1) m = fmaxf(m, __shfl_xor_sync(0xffffffffu, m, o));
            if (lane == 0) rmax_s[r] = m;
        }
    } else {
        const float4 va0 = k0 ? *(const float4*)(v_s + c0w)     : f4z;
        const float4 va1 = k0 ? *(const float4*)(v_s + c0w + 4) : f4z;
        const float4 vb0 = k2 ? *(const float4*)(v_s + 256)     : f4z;
        for (int r = w; r < nt; r += 16) {
            const __half* krow = Kh + (size_t)r * ndp;
            const float u = u_s[r];
            float m = 0.f;
            if (k0) {
                uint4 raw = *(const uint4*)(krow + c0w);
                float2 f;
                f = __half22float2(*(__half2*)&raw.x); m = fmaxf(m, tmul3(u, f.x, va0.x)); m = fmaxf(m, tmul3(u, f.y, va0.y));
                f = __half22float2(*(__half2*)&raw.y); m = fmaxf(m, tmul3(u, f.x, va0.z)); m = fmaxf(m, tmul3(u, f.y, va0.w));
                f = __half22float2(*(__half2*)&raw.z); m = fmaxf(m, tmul3(u, f.x, va1.x)); m = fmaxf(m, tmul3(u, f.y, va1.y));
                f = __half22float2(*(__half2*)&raw.w); m = fmaxf(m, tmul3(u, f.x, va1.z)); m = fmaxf(m, tmul3(u, f.y, va1.w));
            }
            if (k2) {
                uint4 raw = *(const uint4*)(krow + 256);
                float2 f;
                f = __half22float2(*(__half2*)&raw.x); m = fmaxf(m, tmul3(u, f.x, vb0.x)); m = fmaxf(m, tmul3(u, f.y, vb0.y));
                f = __half22float2(*(__half2*)&raw.y); m = fmaxf(m, tmul3(u, f.x, vb0.z)); m = fmaxf(m, tmul3(u, f.y, vb0.w));
            }
            #pragma unroll
            for (int o = 16; o > 0; o >>= 1) m = fmaxf(m, __shfl_xor_sync(0xffffffffu, m, o));
            if (lane == 0) rmax_s[r] = m;
        }
    }
    __syncthreads();

    if (F32) {
        // ---- fp32 epilogue column passes (proven R8) ----
        float cmx = 0.f;
        if (colok) {
            const float vc = v_s[col];
            const float* p = Kf + col + (size_t)p2beg * ndp;
            for (int r = p2beg; r < p2end; r++) { cmx = fmaxf(cmx, tmul3(u_s[r], p[0], vc)); p += ndpS; }
        }
        if (up && colok) scr[col] = cmx;
        __syncthreads();
        if (!up && colok) cmax_s[col] = fmaxf(cmx, scr[col]);
        __syncthreads();

        float colhas = 0.f;
        if (colok) {
            const float vc = v_s[col];
            const float cf = cmax_s[col];
            const float* p = Kf + col + (size_t)p2beg * ndp;
            for (int r = p2beg; r < p2end; r++) {
                float t = tmul3(u_s[r], p[0], vc);
                bool  a = (t == rmax_s[r]) && (t == cf);
                size_t idx = (size_t)r * nd1 + col;
                oT[idx] = t; oA[idx] = a ? 1.f : 0.f;
                if (a) { colhas = 1.f; rhas[r] = 1.f; }    // benign same-value races
                p += ndpS;
            }
        }
        if (up && colok) scr[col] = colhas;
        __syncthreads();
        if (!up && colok) {                                // births row
            colhas = fmaxf(colhas, scr[col]);
            size_t bidx = (size_t)nt * nd1 + col;
            oT[bidx] = __fmul_rn(u_tF, v_s[col]);
            oA[bidx] = (colhas > 0.f) ? 0.f : 1.f;
        }
        __syncthreads();
    } else {
        // ---- fp16 epilogue: col-pair x quarter (proven R9) ----
        const float vc0 = (c0 < nd) ? v_s[c0] : 0.f;
        const float vc1 = (c1 < nd) ? v_s[c1] : 0.f;

        float cmx0 = 0.f, cmx1 = 0.f;
        {
            const __half2* p = (const __half2*)Kh + (size_t)rqb * ndp_2 + cp;
            for (int r = rqb; r < rqe; r++) {
                float2 kk = __half22float2(p[0]);
                cmx0 = fmaxf(cmx0, tmul3(u_s[r], kk.x, vc0));
                cmx1 = fmaxf(cmx1, tmul3(u_s[r], kk.y, vc1));
                p += ndp_2;
            }
        }
        if (qq > 0) *(float2*)(scr2 + (size_t)(qq - 1) * 256 + 2 * cp) = make_float2(cmx0, cmx1);
        __syncthreads();
        if (qq == 0) {
            #pragma unroll
            for (int k = 0; k < 3; k++) {
                float2 o = *(float2*)(scr2 + (size_t)k * 256 + 2 * cp);
                cmx0 = fmaxf(cmx0, o.x); cmx1 = fmaxf(cmx1, o.y);
            }
            if (c0 < nd) cmax_s[c0] = cmx0;
            if (c1 < nd) cmax_s[c1] = cmx1;
        }
        __syncthreads();

        const float cf0 = (c0 < nd) ? cmax_s[c0] : 0.f;
        const float cf1 = (c1 < nd) ? cmax_s[c1] : 0.f;
        float ch0 = 0.f, ch1 = 0.f;
        {
            const __half2* p = (const __half2*)Kh + (size_t)rqb * ndp_2 + cp;
            for (int r = rqb; r < rqe; r++) {
                float2 kk = __half22float2(p[0]);
                float  rf = rmax_s[r];
                size_t rb = (size_t)r * nd1;
                if (c0 < nd) {
                    float t = tmul3(u_s[r], kk.x, vc0);
                    bool  a = (t == rf) && (t == cf0);
                    oT[rb + c0] = t; oA[rb + c0] = a ? 1.f : 0.f;
                    if (a) { ch0 = 1.f; rhas[r] = 1.f; }
                }
                if (c1 < nd) {
                    float t = tmul3(u_s[r], kk.y, vc1);
                    bool  a = (t == rf) && (t == cf1);
                    oT[rb + c1] = t; oA[rb + c1] = a ? 1.f : 0.f;
                    if (a) { ch1 = 1.f; rhas[r] = 1.f; }
                }
                p += ndp_2;
            }
        }
        if (qq > 0) *(float2*)(scr2 + (size_t)(qq - 1) * 256 + 2 * cp) = make_float2(ch0, ch1);
        __syncthreads();
        if (qq == 0) {
            #pragma unroll
            for (int k = 0; k < 3; k++) {
                float2 o = *(float2*)(scr2 + (size_t)k * 256 + 2 * cp);
                ch0 = fmaxf(ch0, o.x); ch1 = fmaxf(ch1, o.y);
            }
            size_t bb = (size_t)nt * nd1;                  // births row
            if (c0 < nd) { oT[bb + c0] = __fmul_rn(u_tF, vc0); oA[bb + c0] = (ch0 > 0.f) ? 0.f : 1.f; }
            if (c1 < nd) { oT[bb + c1] = __fmul_rn(u_tF, vc1); oA[bb + c1] = (ch1 > 0.f) ? 0.f : 1.f; }
        }
        __syncthreads();
    }

    if (tid < nt) {                                        // deaths column
        size_t idx = (size_t)tid * nd1 + nd;
        oT[idx] = __fmul_rn(u_s[tid], v_dF);
        oA[idx] = (rhas[tid] > 0.f) ? 0.f : 1.f;
    }
    if (tid == 0) {                                        // corner
        size_t idx = (size_t)nt * nd1 + nd;
        oT[idx] = __fmul_rn(u_tF, v_dF);
        oA[idx] = 0.f;
    }
    const int length = (nt + 1) * nd1;                     // zero pad tail
    for (int k = length + tid; k < L_PAD; k += NTHREADS) { oT[k] = 0.f; oA[k] = 0.f; }
}

__global__ void __launch_bounds__(NTHREADS, 1)
assoc_kernel(const float* __restrict__ aff, const int* __restrict__ ndet,
             const int* __restrict__ ntrk, float* __restrict__ outT,
             float* __restrict__ outA, int Bn)
{
    extern __shared__ float sm[];
    const int tid = threadIdx.x;

    // ---- LPT remap: block bid handles the example with cost-rank bid ----
    int* cost_s = (int*)(sm + RMAX_OFF);    // [Bn] (Bn <= 512)
    int* pick_s = (int*)(sm + PICK_OFF);    // [1]
    if (tid < Bn) cost_s[tid] = (ntrk[tid] + 1) * (ndet[tid] + 1);
    __syncthreads();
    if (tid < Bn) {
        const int myc = cost_s[tid];
        int rank = 0;
        for (int j = 0; j < Bn; j++) {
            int cj = cost_s[j];
            rank += (cj > myc) || (cj == myc && j < tid);
        }
        if (rank == (int)blockIdx.x) *pick_s = tid;
    }
    __syncthreads();
    const int b = *pick_s;
    __syncthreads();   // everyone has read b before sm is reused

    const int nd = ndet[b];
    const int nt = ntrk[b];
    const float* affb = aff + (size_t)b * (256 * 256);
    float* oT = outT + (size_t)b * L_PAD;
    float* oA = outA + (size_t)b * L_PAD;

    int ndp4 = (nd + 3) & ~3;
    if (((ndp4 >> 2) & 1) == 0) ndp4 += 4;
    if (nt * ndp4 <= KCAP) run_ex<true >(affb, nt, nd, oT, oA, sm);
    else                   run_ex<false>(affb, nt, nd, oT, oA, sm);
}

extern "C" void kernel_launch(void* const* d_in, const int* in_sizes, int n_in,
                              void* d_out, int out_size)
{
    const float* aff  = (const float*)d_in[0];
    const int*   ndet = (const int*)d_in[1];
    const int*   ntrk = (const int*)d_in[2];
    const int    Bn   = in_sizes[1];

    float* out  = (float*)d_out;
    float* outA = out + (size_t)(out_size / 2);   // [t_flat | a_flat]

    cudaFuncSetAttribute(assoc_kernel, cudaFuncAttributeMaxDynamicSharedMemorySize, SMEM_BYTES);
    assoc_kernel<<<Bn, NTHREADS, SMEM_BYTES>>>(aff, ndet, ntrk, out, outA, Bn);
}

// round 13
// speedup vs baseline: 2.2012x; 2.2012x over previous
#include <cuda_runtime.h>
#include <cuda_fp16.h>

// B=256, T_MAX=D_MAX=256, TP=DP=257
#define NTHREADS 512
#define L_PAD    66049          // 257*257
#define EPS_C    1e-12f

// Shared layout (floats)
#define U_OFF    0              // u[260]
#define V_OFF    260            // v[260]
#define RMAX_OFF 520            // row max [260]     (reused as cost[] during remap)
#define RHAS_OFF 780            // row-has-assignment flags [260]
#define CMAX_OFF 1040           // col max [260]
#define SUP_OFF  1300           // per-warp sum(u) partials [16]
#define SVP_OFF  1316           // per-warp sum(v) partials [16]
#define SCR_OFF  1332           // half-split combine scratch [256]
#define SCR2_OFF 1588           // fp16 quarter-combine scratch [768] (3 x 256)
#define PICK_OFF 2356           // chosen example index [1]
#define K_OFF    2360
#define SMEM_FLOATS 58112       // 232448 B / 4
#define KCAP     (SMEM_FLOATS - K_OFF)   // 55752 fp32 slots
#define SMEM_BYTES (SMEM_FLOATS * 4)

// Deterministic 3-way product: bit-identical across all transport recomputes.
__device__ __forceinline__ float tmul3(float u, float k, float v) {
    return __fmul_rn(__fmul_rn(u, k), v);
}

template<bool F32>
__device__ void run_ex(const float* __restrict__ aff, int nt, int nd,
                       float* __restrict__ oT, float* __restrict__ oA,
                       float* sm)
{
    const int tid  = threadIdx.x;
    const int lane = tid & 31;
    const int w    = tid >> 5;

    // Row pitch: odd multiple of 4 (fp32) / 8 (fp16) -> conflict-free
    // strided row loads in pass 1 (8-lane wavefront quads form a bijection).
    int ndp;
    if (F32) { ndp = (nd + 3) & ~3; if (((ndp >> 2) & 1) == 0) ndp += 4; }
    else     { ndp = (nd + 7) & ~7; if (((ndp >> 3) & 1) == 0) ndp += 8; }

    // Contiguous half-split boundaries for pass 1 (vector-aligned).
    const int ndh = F32 ? ((ndp >> 1) & ~3) : ((ndp >> 1) & ~7);
    const int nth = (nt >> 1) & ~3;

    float*  u_s    = sm + U_OFF;
    float*  v_s    = sm + V_OFF;
    float*  rmax_s = sm + RMAX_OFF;
    float*  rhas   = sm + RHAS_OFF;
    float*  cmax_s = sm + CMAX_OFF;
    float*  sup    = sm + SUP_OFF;
    float*  svp    = sm + SVP_OFF;
    float*  scr    = sm + SCR_OFF;
    float*  scr2   = sm + SCR2_OFF;
    float*  Kf     = sm + K_OFF;
    __half* Kh     = (__half*)(sm + K_OFF);

    // Pass-1 identities: thread t and t+256 share row (t&255), each takes a half.
    const int  row   = tid & 255;
    const bool up    = tid >= 256;
    const bool rowok = row < nt;
    const int  p1beg = up ? ndh : 0;
    const int  p1end = up ? ndp : ndh;

    // fp32 pass-2 identities (half rows per column; proven R8)
    const int  col   = row;
    const bool colok = col < nd;
    const int  p2beg = up ? nth : 0;
    const int  p2end = up ? nt  : nth;

    // fp16 pass-2 identities: column pair (2cp, 2cp+1) x row quarter qq (proven R9)
    const int cp   = tid & 127;
    const int qq   = tid >> 7;
    const int c0   = 2 * cp, c1 = 2 * cp + 1;
    const int qb1  = (nt >> 2) & ~3;
    const int qb2  = (nt >> 1) & ~3;
    const int qb3  = ((3 * nt) >> 2) & ~3;
    const int rqb  = (qq == 0) ? 0   : (qq == 1) ? qb1 : (qq == 2) ? qb2 : qb3;
    const int rqe  = (qq == 0) ? qb1 : (qq == 1) ? qb2 : (qq == 2) ? qb3 : nt;
    const int ndp_h2 = ndp >> 1;

    // ---- Pre-zero K region (padding must be exactly 0) ----
    const int kwords = F32 ? nt * ndp : (nt * ndp) >> 1;   // floats, mult of 4
    for (int i = tid * 4; i < kwords; i += NTHREADS * 4)
        *(float4*)(Kf + i) = make_float4(0.f, 0.f, 0.f, 0.f);

    // init v0 = 1 on c<=nd; interior partial sum = nd
    for (int c = tid; c < 260; c += NTHREADS) v_s[c] = (c <= nd) ? 1.f : 0.f;
    if (tid < 16) svp[tid] = (tid == 0) ? (float)nd : 0.f;
    __syncthreads();

    // ---- Build K = exp(10*aff) on interior ----
    {
        const int cq0 = F32 ? 4 * lane : 8 * lane;
        const int cq1 = 4 * lane + 128;
        for (int r = w; r < nt; r += 16) {
            const float* arow = aff + (size_t)r * 256;
            if (F32) {
                float* krow = Kf + (size_t)r * ndp;
                if (cq0 < nd) {
                    float x[4];
                    #pragma unroll
                    for (int i = 0; i < 4; i++) { int c = cq0 + i; x[i] = (c < nd) ? __expf(10.0f * arow[c]) : 0.f; }
                    *(float4*)(krow + cq0) = make_float4(x[0], x[1], x[2], x[3]);
                }
                if (cq1 < nd) {
                    float x[4];
                    #pragma unroll
                    for (int i = 0; i < 4; i++) { int c = cq1 + i; x[i] = (c < nd) ? __expf(10.0f * arow[c]) : 0.f; }
                    *(float4*)(krow + cq1) = make_float4(x[0], x[1], x[2], x[3]);
                }
            } else {
                __half* krow = Kh + (size_t)r * ndp;
                if (cq0 < nd) {
                    __half h[8];
                    #pragma unroll
                    for (int i = 0; i < 8; i++) { int c = cq0 + i; h[i] = __float2half_rn((c < nd) ? __expf(10.0f * arow[c]) : 0.f); }
                    *(uint4*)(krow + cq0) = *(uint4*)h;
                }
            }
        }
    }
    __syncthreads();

    const float ndf = (float)nd, ntf = (float)nt;
    const int   ndpS = ndp, ndp2 = 2 * ndp, ndp3 = 3 * ndp, ndp4s = 4 * ndp;

    // ================= up to 100 Sinkhorn iterations =================
    // Early exit when v is bitwise stationary across one iteration: from a
    // fixed v the map reproduces u and v exactly (identical fp ops, identical
    // order), so the remaining iterations are identity — outputs bit-identical
    // to the full 100.
    for (int it = 0; it < 100; ++it) {
        // ---- Pass 1: u_r = 1/((Kv)_r + v[nd] + eps), half-split ----
        float sumv = v_s[nd];
        #pragma unroll
        for (int k = 0; k < 16; k++) sumv += svp[k];
        const float u_top = ndf / (sumv + EPS_C);
        const float v_dum = v_s[nd];

        float dot = 0.f;
        if (rowok) {
            float a0 = 0.f, a1 = 0.f, a2 = 0.f, a3 = 0.f;
            if (F32) {
                const float* krow = Kf + (size_t)row * ndp;
                #pragma unroll 4
                for (int c = p1beg; c < p1end; c += 4) {
                    float4 kk = *(const float4*)(krow + c);
                    float4 vv = *(const float4*)(v_s + c);     // warp-uniform broadcast
                    a0 = fmaf(kk.x, vv.x, a0); a1 = fmaf(kk.y, vv.y, a1);
                    a2 = fmaf(kk.z, vv.z, a2); a3 = fmaf(kk.w, vv.w, a3);
                }
            } else {
                const __half* krow = Kh + (size_t)row * ndp;
                #pragma unroll 2
                for (int c = p1beg; c < p1end; c += 8) {
                    uint4  raw = *(const uint4*)(krow + c);
                    float4 v0  = *(const float4*)(v_s + c);
                    float4 v1  = *(const float4*)(v_s + c + 4);
                    float2 f;
                    f = __half22float2(*(__half2*)&raw.x); a0 = fmaf(f.x, v0.x, a0); a1 = fmaf(f.y, v0.y, a1);
                    f = __half22float2(*(__half2*)&raw.y); a2 = fmaf(f.x, v0.z, a2); a3 = fmaf(f.y, v0.w, a3);
                    f = __half22float2(*(__half2*)&raw.z); a0 = fmaf(f.x, v1.x, a0); a1 = fmaf(f.y, v1.y, a1);
                    f = __half22float2(*(__half2*)&raw.w); a2 = fmaf(f.x, v1.z, a2); a3 = fmaf(f.y, v1.w, a3);
                }
            }
            dot = (a0 + a1) + (a2 + a3);
        }
        if (up && rowok) scr[row] = dot;
        __syncthreads();                                   // B1

        float u_val = 0.f;
        if (!up && rowok) {
            float d = dot + scr[row];
            u_val = 1.0f / (d + v_dum + EPS_C);
            u_s[row] = u_val;
        }
        if (tid == 0) u_s[nt] = u_top;
        float su = u_val;                                  // 0 for upper half
        #pragma unroll
        for (int o = 16; o > 0; o >>= 1) su += __shfl_xor_sync(0xffffffffu, su, o);
        if (lane == 0) sup[w] = su;
        __syncthreads();                                   // B2

        // ---- Pass 2: v_c = 1/((K^T u)_c + u_top + eps) ----
        float sumu = u_top;
        #pragma unroll
        for (int k = 0; k < 16; k++) sumu += sup[k];
        const float v_dnew = ntf / (sumu + EPS_C);

        int conv = 1;                                      // per-thread stationarity vote
        if (F32) {
            float z = 0.f;
            if (colok) {
                float z0 = 0.f, z1 = 0.f, z2 = 0.f, z3 = 0.f;
                int r = p2beg;
                const float* p = Kf + col + (size_t)p2beg * ndp;
                for (; r + 3 < p2end; r += 4) {
                    float4 uu = *(const float4*)(u_s + r);     // broadcast (r mult of 4)
                    z0 = fmaf(p[0],     uu.x, z0);
                    z1 = fmaf(p[ndpS],  uu.y, z1);
                    z2 = fmaf(p[ndp2],  uu.z, z2);
                    z3 = fmaf(p[ndp3],  uu.w, z3);
                    p += ndp4s;
                }
                for (; r < p2end; r++) { z0 = fmaf(p[0], u_s[r], z0); p += ndpS; }
                z = (z0 + z1) + (z2 + z3);
            }
            if (up && colok) scr[col] = z;
            __syncthreads();                               // B3

            float myv = 0.f;
            if (!up && colok) {
                float zz = (z + scr[col]) + u_top;
                myv = 1.0f / (zz + EPS_C);
                float vold = v_s[col];
                conv = (__float_as_uint(myv) == __float_as_uint(vold));
                v_s[col] = myv;
            }
            if (tid == 0) {
                conv &= (__float_as_uint(v_dnew) == __float_as_uint(v_dum));
                v_s[nd] = v_dnew;
            }
            float sv = myv;
            #pragma unroll
            for (int o = 16; o > 0; o >>= 1) sv += __shfl_xor_sync(0xffffffffu, sv, o);
            if (lane == 0) svp[w] = sv;
            if (__syncthreads_and(conv)) break;            // B4 + exact early exit
        } else {
            // fp16: col-pair half2 loads, 4-way row quarters (proven R9).
            float zxa = 0.f, zya = 0.f, zxb = 0.f, zyb = 0.f;
            {
                const __half2* p = (const __half2*)Kh + (size_t)rqb * ndp_h2 + cp;
                int r = rqb;
                for (; r + 3 < rqe; r += 4) {
                    float4 uu = *(const float4*)(u_s + r);     // broadcast (rqb mult of 4)
                    float2 k0 = __half22float2(p[0]);
                    float2 k1 = __half22float2(p[ndp_h2]);
                    float2 k2 = __half22float2(p[2 * ndp_h2]);
                    float2 k3 = __half22float2(p[3 * ndp_h2]);
                    zxa = fmaf(k0.x, uu.x, zxa); zya = fmaf(k0.y, uu.x, zya);
                    zxb = fmaf(k1.x, uu.y, zxb); zyb = fmaf(k1.y, uu.y, zyb);
                    zxa = fmaf(k2.x, uu.z, zxa); zya = fmaf(k2.y, uu.z, zya);
                    zxb = fmaf(k3.x, uu.w, zxb); zyb = fmaf(k3.y, uu.w, zyb);
                    p += 4 * ndp_h2;
                }
                for (; r < rqe; r++) {
                    float2 kk = __half22float2(p[0]);
                    float  ur = u_s[r];
                    zxa = fmaf(kk.x, ur, zxa); zya = fmaf(kk.y, ur, zya);
                    p += ndp_h2;
                }
            }
            float zx = zxa + zxb, zy = zya + zyb;
            if (qq > 0) *(float2*)(scr2 + (size_t)(qq - 1) * 256 + 2 * cp) = make_float2(zx, zy);
            __syncthreads();                               // B3

            float svq = 0.f;
            if (qq == 0) {
                #pragma unroll
                for (int k = 0; k < 3; k++) {
                    float2 o = *(float2*)(scr2 + (size_t)k * 256 + 2 * cp);
                    zx += o.x; zy += o.y;
                }
                if (c0 < nd) {
                    float v0 = 1.0f / ((zx + u_top) + EPS_C);
                    conv &= (__float_as_uint(v0) == __float_as_uint(v_s[c0]));
                    v_s[c0] = v0; svq += v0;
                }
                if (c1 < nd) {
                    float v1 = 1.0f / ((zy + u_top) + EPS_C);
                    conv &= (__float_as_uint(v1) == __float_as_uint(v_s[c1]));
                    v_s[c1] = v1; svq += v1;
                }
            }
            if (tid == 0) {
                conv &= (__float_as_uint(v_dnew) == __float_as_uint(v_dum));
                v_s[nd] = v_dnew;
            }
            #pragma unroll
            for (int o = 16; o > 0; o >>= 1) svq += __shfl_xor_sync(0xffffffffu, svq, o);
            if (lane == 0) svp[w] = svq;
            if (__syncthreads_and(conv)) break;            // B4 + exact early exit
        }
    }

    // ================= Epilogue =================
    const float v_dF = v_s[nd];
    const float u_tF = u_s[nt];
    const int   nd1  = nd + 1;

    if (tid < 260) rhas[tid] = 0.f;

    // E1: row max (half-split per row)
    float rmx = 0.f;
    if (rowok) {
        const float u = u_s[row];
        if (F32) {
            const float* krow = Kf + (size_t)row * ndp;
            #pragma unroll 4
            for (int c = p1beg; c < p1end; c += 4) {
                float4 kk = *(const float4*)(krow + c);
                float4 vv = *(const float4*)(v_s + c);
                rmx = fmaxf(rmx, tmul3(u, kk.x, vv.x));
                rmx = fmaxf(rmx, tmul3(u, kk.y, vv.y));
                rmx = fmaxf(rmx, tmul3(u, kk.z, vv.z));
                rmx = fmaxf(rmx, tmul3(u, kk.w, vv.w));
            }
        } else {
            const __half* krow = Kh + (size_t)row * ndp;
            for (int c = p1beg; c < p1end; c++)
                rmx = fmaxf(rmx, tmul3(u, __half2float(krow[c]), v_s[c]));
        }
    }
    if (up && rowok) scr[row] = rmx;
    __syncthreads();
    if (!up && rowok) rmax_s[row] = fmaxf(rmx, scr[row]);
    __syncthreads();

    if (F32) {
        // ---- fp32 epilogue column passes (proven R8) ----
        float cmx = 0.f;
        if (colok) {
            const float vc = v_s[col];
            const float* p = Kf + col + (size_t)p2beg * ndp;
            for (int r = p2beg; r < p2end; r++) { cmx = fmaxf(cmx, tmul3(u_s[r], p[0], vc)); p += ndpS; }
        }
        if (up && colok) scr[col] = cmx;
        __syncthreads();
        if (!up && colok) cmax_s[col] = fmaxf(cmx, scr[col]);
        __syncthreads();

        float colhas = 0.f;
        if (colok) {
            const float vc = v_s[col];
            const float cf = cmax_s[col];
            const float* p = Kf + col + (size_t)p2beg * ndp;
            for (int r = p2beg; r < p2end; r++) {
                float t = tmul3(u_s[r], p[0], vc);
                bool  a = (t == rmax_s[r]) && (t == cf);
                size_t idx = (size_t)r * nd1 + col;
                oT[idx] = t; oA[idx] = a ? 1.f : 0.f;
                if (a) { colhas = 1.f; rhas[r] = 1.f; }    // benign same-value races
                p += ndpS;
            }
        }
        if (up && colok) scr[col] = colhas;
        __syncthreads();
        if (!up && colok) {                                // births row
            colhas = fmaxf(colhas, scr[col]);
            size_t bidx = (size_t)nt * nd1 + col;
            oT[bidx] = __fmul_rn(u_tF, v_s[col]);
            oA[bidx] = (colhas > 0.f) ? 0.f : 1.f;
        }
        __syncthreads();
    } else {
        // ---- fp16 epilogue: col-pair x quarter layout (proven R9) ----
        const float vc0 = (c0 < nd) ? v_s[c0] : 0.f;
        const float vc1 = (c1 < nd) ? v_s[c1] : 0.f;

        // E2a: col max
        float cmx0 = 0.f, cmx1 = 0.f;
        {
            const __half2* p = (const __half2*)Kh + (size_t)rqb * ndp_h2 + cp;
            for (int r = rqb; r < rqe; r++) {
                float2 kk = __half22float2(p[0]);
                cmx0 = fmaxf(cmx0, tmul3(u_s[r], kk.x, vc0));
                cmx1 = fmaxf(cmx1, tmul3(u_s[r], kk.y, vc1));
                p += ndp_h2;
            }
        }
        if (qq > 0) *(float2*)(scr2 + (size_t)(qq - 1) * 256 + 2 * cp) = make_float2(cmx0, cmx1);
        __syncthreads();
        if (qq == 0) {
            #pragma unroll
            for (int k = 0; k < 3; k++) {
                float2 o = *(float2*)(scr2 + (size_t)k * 256 + 2 * cp);
                cmx0 = fmaxf(cmx0, o.x); cmx1 = fmaxf(cmx1, o.y);
            }
            if (c0 < nd) cmax_s[c0] = cmx0;
            if (c1 < nd) cmax_s[c1] = cmx1;
        }
        __syncthreads();

        // E2b: write pass over quarter's rows for both cols
        const float cf0 = (c0 < nd) ? cmax_s[c0] : 0.f;
        const float cf1 = (c1 < nd) ? cmax_s[c1] : 0.f;
        float ch0 = 0.f, ch1 = 0.f;
        {
            const __half2* p = (const __half2*)Kh + (size_t)rqb * ndp_h2 + cp;
            for (int r = rqb; r < rqe; r++) {
                float2 kk = __half22float2(p[0]);
                float  rf = rmax_s[r];
                size_t rb = (size_t)r * nd1;
                if (c0 < nd) {
                    float t = tmul3(u_s[r], kk.x, vc0);
                    bool  a = (t == rf) && (t == cf0);
                    oT[rb + c0] = t; oA[rb + c0] = a ? 1.f : 0.f;
                    if (a) { ch0 = 1.f; rhas[r] = 1.f; }
                }
                if (c1 < nd) {
                    float t = tmul3(u_s[r], kk.y, vc1);
                    bool  a = (t == rf) && (t == cf1);
                    oT[rb + c1] = t; oA[rb + c1] = a ? 1.f : 0.f;
                    if (a) { ch1 = 1.f; rhas[r] = 1.f; }
                }
                p += ndp_h2;
            }
        }
        if (qq > 0) *(float2*)(scr2 + (size_t)(qq - 1) * 256 + 2 * cp) = make_float2(ch0, ch1);
        __syncthreads();
        if (qq == 0) {
            #pragma unroll
            for (int k = 0; k < 3; k++) {
                float2 o = *(float2*)(scr2 + (size_t)k * 256 + 2 * cp);
                ch0 = fmaxf(ch0, o.x); ch1 = fmaxf(ch1, o.y);
            }
            size_t bb = (size_t)nt * nd1;                  // births row
            if (c0 < nd) { oT[bb + c0] = __fmul_rn(u_tF, vc0); oA[bb + c0] = (ch0 > 0.f) ? 0.f : 1.f; }
            if (c1 < nd) { oT[bb + c1] = __fmul_rn(u_tF, vc1); oA[bb + c1] = (ch1 > 0.f) ? 0.f : 1.f; }
        }
        __syncthreads();
    }

    if (tid < nt) {                                      // deaths column
        size_t idx = (size_t)tid * nd1 + nd;
        oT[idx] = __fmul_rn(u_s[tid], v_dF);
        oA[idx] = (rhas[tid] > 0.f) ? 0.f : 1.f;
    }
    if (tid == 0) {                                      // corner
        size_t idx = (size_t)nt * nd1 + nd;
        oT[idx] = __fmul_rn(u_tF, v_dF);
        oA[idx] = 0.f;
    }
    const int length = (nt + 1) * nd1;                   // zero pad tail
    for (int k = length + tid; k < L_PAD; k += NTHREADS) { oT[k] = 0.f; oA[k] = 0.f; }
}

__global__ void __launch_bounds__(NTHREADS, 1)
assoc_kernel(const float* __restrict__ aff, const int* __restrict__ ndet,
             const int* __restrict__ ntrk, float* __restrict__ outT,
             float* __restrict__ outA, int Bn)
{
    extern __shared__ float sm[];
    const int tid = threadIdx.x;

    // ---- LPT remap: block bid handles the example with cost-rank bid ----
    int* cost_s = (int*)(sm + RMAX_OFF);    // [Bn] (Bn <= 512)
    int* pick_s = (int*)(sm + PICK_OFF);    // [1]
    if (tid < Bn) cost_s[tid] = (ntrk[tid] + 1) * (ndet[tid] + 1);
    __syncthreads();
    if (tid < Bn) {
        const int myc = cost_s[tid];
        int rank = 0;
        for (int j = 0; j < Bn; j++) {
            int cj = cost_s[j];
            rank += (cj > myc) || (cj == myc && j < tid);
        }
        if (rank == (int)blockIdx.x) *pick_s = tid;
    }
    __syncthreads();
    const int b = *pick_s;
    __syncthreads();   // everyone has read b before sm is reused

    const int nd = ndet[b];
    const int nt = ntrk[b];
    const float* affb = aff + (size_t)b * (256 * 256);
    float* oT = outT + (size_t)b * L_PAD;
    float* oA = outA + (size_t)b * L_PAD;

    int ndp4 = (nd + 3) & ~3;
    if (((ndp4 >> 2) & 1) == 0) ndp4 += 4;
    if (nt * ndp4 <= KCAP) run_ex<true >(affb, nt, nd, oT, oA, sm);
    else                   run_ex<false>(affb, nt, nd, oT, oA, sm);
}

extern "C" void kernel_launch(void* const* d_in, const int* in_sizes, int n_in,
                              void* d_out, int out_size)
{
    const float* aff  = (const float*)d_in[0];
    const int*   ndet = (const int*)d_in[1];
    const int*   ntrk = (const int*)d_in[2];
    const int    Bn   = in_sizes[1];

    float* out  = (float*)d_out;
    float* outA = out + (size_t)(out_size / 2);   // [t_flat | a_flat]

    cudaFuncSetAttribute(assoc_kernel, cudaFuncAttributeMaxDynamicSharedMemorySize, SMEM_BYTES);
    assoc_kernel<<<Bn, NTHREADS, SMEM_BYTES>>>(aff, ndet, ntrk, out, outA, Bn);
}